// round 9
// baseline (speedup 1.0000x reference)
#include <cuda_runtime.h>
#include <cuda_bf16.h>
#include <math.h>
#include <stdint.h>

#define B_ 32
#define S_ 4096
#define E_ 512
#define D_ 512
#define H_ 512

#define MT 128          // CTA rows
#define NT 128          // CTA cols (h)
#define KC 32           // K chunk (fp32 source)
#define NCHUNK (E_ / KC)    // 16
#define NTILES (H_ / NT)    // 4
#define ASTR 40         // smem row stride in bf16 (pad: conflict-free frag loads)

// ---------------- scratch (__device__ globals; no allocs allowed) ----------
__device__ float          g_dec_h[B_ * H_];
__device__ __nv_bfloat16  g_Whi[H_ * E_];
__device__ __nv_bfloat16  g_Wlo[H_ * E_];
__device__ float          g_scpart[B_ * S_ * NTILES];
__device__ unsigned char  g_flpart[B_ * S_ * NTILES];
__device__ float          g_scores[B_ * S_];
__device__ float          g_attn[B_ * S_];
__device__ float          g_partial[B_ * 8 * E_];

// ---------------- mma.sync m16n8k16 bf16 (base ISA, valid on sm_103) -------
__device__ __forceinline__ void mma16816(float* d, const uint32_t* a,
                                         const uint32_t* b) {
    asm volatile(
        "mma.sync.aligned.m16n8k16.row.col.f32.bf16.bf16.f32 "
        "{%0,%1,%2,%3}, {%4,%5,%6,%7}, {%8,%9}, {%0,%1,%2,%3};"
        : "+f"(d[0]), "+f"(d[1]), "+f"(d[2]), "+f"(d[3])
        : "r"(a[0]), "r"(a[1]), "r"(a[2]), "r"(a[3]), "r"(b[0]), "r"(b[1]));
}

// ---------------------------------------------------------------------------
// Kernel A: convert W_enc to bf16 hi/lo (1 MB, once per launch)
// ---------------------------------------------------------------------------
__global__ void k_convW(const float* __restrict__ W) {
    int i = blockIdx.x * 512 + threadIdx.x;
    float w = W[i];
    __nv_bfloat16 hi = __float2bfloat16_rn(w);
    __nv_bfloat16 lo = __float2bfloat16_rn(w - __bfloat162float(hi));
    g_Whi[i] = hi;
    g_Wlo[i] = lo;
}

// ---------------------------------------------------------------------------
// Kernel 0: dec_h[b,h] = decoder_hidden[b,:] . W_dec[h,:] + b_dec[h]
// ---------------------------------------------------------------------------
__global__ void k_dec(const float* __restrict__ dec,
                      const float* __restrict__ Wd,
                      const float* __restrict__ bd) {
    int b = blockIdx.x;
    int warp = threadIdx.x >> 5, lane = threadIdx.x & 31, nw = blockDim.x >> 5;
    const float* drow = dec + (long)b * D_;
    for (int h = warp; h < H_; h += nw) {
        const float* wrow = Wd + (long)h * D_;
        float s = 0.f;
        for (int e = lane; e < D_; e += 32) s = fmaf(drow[e], wrow[e], s);
        #pragma unroll
        for (int o = 16; o; o >>= 1) s += __shfl_xor_sync(0xffffffffu, s, o);
        if (lane == 0) g_dec_h[b * H_ + h] = s + bd[h];
    }
}

// ---------------------------------------------------------------------------
// Kernel 1: bf16 hi/lo 3-pass HMMA GEMM + fused Bahdanau score epilogue.
// CTA = 128 rows x 128 h.  bid = mtile*4 + ntile.  8 warps as 4(M) x 2(N).
// ---------------------------------------------------------------------------
__global__ __launch_bounds__(256, 2)
void k_gemm(const float* __restrict__ X,
            const float* __restrict__ benc,
            const float* __restrict__ v) {
    __shared__ __nv_bfloat16 sAhi[MT * ASTR];
    __shared__ __nv_bfloat16 sAlo[MT * ASTR];
    __shared__ __nv_bfloat16 sBhi[NT * ASTR];
    __shared__ __nv_bfloat16 sBlo[NT * ASTR];
    __shared__ float s_red[MT * 2];
    __shared__ int   s_nzr[MT * 2];
    __shared__ float s_be[NT], s_v[NT], s_dh[NT];

    const int tid = threadIdx.x;
    const int wid = tid >> 5;
    const int lid = tid & 31;
    const int g   = lid >> 2;     // group id (rows / n within 8-blocks)
    const int t   = lid & 3;      // thread-in-group (k pairs)
    const int wm  = wid >> 1;     // warp M index 0..3 (32 rows each)
    const int wn  = wid & 1;      // warp N index 0..1 (64 cols each)

    const int mtile = blockIdx.x >> 2;
    const int ntile = blockIdx.x & 3;
    const int n0    = ntile * NT;
    const int b     = mtile >> 5;          // 32 M-tiles per batch
    const long mbase = (long)mtile * MT;

    float acc[2][8][4];
    #pragma unroll
    for (int mt = 0; mt < 2; mt++)
        #pragma unroll
        for (int nt = 0; nt < 8; nt++)
            #pragma unroll
            for (int c = 0; c < 4; c++) acc[mt][nt][c] = 0.f;

    const float* Xblk = X + mbase * E_;

    for (int ch = 0; ch < NCHUNK; ch++) {
        const int k0 = ch * KC;
        __syncthreads();
        // ---- stage A: 128 x 32 fp32 -> bf16 hi/lo (1024 float4, 4/thread) --
        #pragma unroll
        for (int it = 0; it < 4; it++) {
            int idx = tid + it * 256;
            int row = idx >> 3, q = idx & 7;        // q*4 = k offset
            float4 xv = *(const float4*)(Xblk + (long)row * E_ + k0 + q * 4);
            __nv_bfloat16 h0 = __float2bfloat16_rn(xv.x);
            __nv_bfloat16 h1 = __float2bfloat16_rn(xv.y);
            __nv_bfloat16 h2 = __float2bfloat16_rn(xv.z);
            __nv_bfloat16 h3 = __float2bfloat16_rn(xv.w);
            __nv_bfloat16 l0 = __float2bfloat16_rn(xv.x - __bfloat162float(h0));
            __nv_bfloat16 l1 = __float2bfloat16_rn(xv.y - __bfloat162float(h1));
            __nv_bfloat16 l2 = __float2bfloat16_rn(xv.z - __bfloat162float(h2));
            __nv_bfloat16 l3 = __float2bfloat16_rn(xv.w - __bfloat162float(h3));
            __nv_bfloat162 ph0 = __halves2bfloat162(h0, h1);
            __nv_bfloat162 ph1 = __halves2bfloat162(h2, h3);
            __nv_bfloat162 pl0 = __halves2bfloat162(l0, l1);
            __nv_bfloat162 pl1 = __halves2bfloat162(l2, l3);
            uint2 uh = make_uint2(*(uint32_t*)&ph0, *(uint32_t*)&ph1);
            uint2 ul = make_uint2(*(uint32_t*)&pl0, *(uint32_t*)&pl1);
            *(uint2*)&sAhi[row * ASTR + q * 4] = uh;
            *(uint2*)&sAlo[row * ASTR + q * 4] = ul;
        }
        // ---- stage B: 128 h x 32 k from preconverted bf16 (512 uint4) -----
        #pragma unroll
        for (int it = 0; it < 2; it++) {
            int idx = tid + it * 256;
            int row = idx >> 2, q = idx & 3;        // q*8 = k offset
            long ge = (long)(n0 + row) * E_ + k0 + q * 8;
            *(uint4*)&sBhi[row * ASTR + q * 8] = *(const uint4*)(g_Whi + ge);
            *(uint4*)&sBlo[row * ASTR + q * 8] = *(const uint4*)(g_Wlo + ge);
        }
        __syncthreads();

        // ---- 2 k16 steps x 3 hi/lo passes ----------------------------------
        #pragma unroll
        for (int ks = 0; ks < 2; ks++) {
            const int kb = ks * 16 + t * 2;
            uint32_t ah[2][4], al[2][4], bb[8][2];
            #pragma unroll
            for (int mt = 0; mt < 2; mt++) {
                int rb = wm * 32 + mt * 16 + g;
                ah[mt][0] = *(uint32_t*)&sAhi[rb * ASTR + kb];
                ah[mt][1] = *(uint32_t*)&sAhi[(rb + 8) * ASTR + kb];
                ah[mt][2] = *(uint32_t*)&sAhi[rb * ASTR + kb + 8];
                ah[mt][3] = *(uint32_t*)&sAhi[(rb + 8) * ASTR + kb + 8];
            }
            #pragma unroll
            for (int nt = 0; nt < 8; nt++) {
                int nr = wn * 64 + nt * 8 + g;
                bb[nt][0] = *(uint32_t*)&sBhi[nr * ASTR + kb];
                bb[nt][1] = *(uint32_t*)&sBhi[nr * ASTR + kb + 8];
            }
            #pragma unroll
            for (int mt = 0; mt < 2; mt++)
                #pragma unroll
                for (int nt = 0; nt < 8; nt++)
                    mma16816(acc[mt][nt], ah[mt], bb[nt]);   // hi*hi
            #pragma unroll
            for (int mt = 0; mt < 2; mt++) {
                int rb = wm * 32 + mt * 16 + g;
                al[mt][0] = *(uint32_t*)&sAlo[rb * ASTR + kb];
                al[mt][1] = *(uint32_t*)&sAlo[(rb + 8) * ASTR + kb];
                al[mt][2] = *(uint32_t*)&sAlo[rb * ASTR + kb + 8];
                al[mt][3] = *(uint32_t*)&sAlo[(rb + 8) * ASTR + kb + 8];
            }
            #pragma unroll
            for (int mt = 0; mt < 2; mt++)
                #pragma unroll
                for (int nt = 0; nt < 8; nt++)
                    mma16816(acc[mt][nt], al[mt], bb[nt]);   // lo*hi
            #pragma unroll
            for (int nt = 0; nt < 8; nt++) {
                int nr = wn * 64 + nt * 8 + g;
                bb[nt][0] = *(uint32_t*)&sBlo[nr * ASTR + kb];
                bb[nt][1] = *(uint32_t*)&sBlo[nr * ASTR + kb + 8];
            }
            #pragma unroll
            for (int mt = 0; mt < 2; mt++)
                #pragma unroll
                for (int nt = 0; nt < 8; nt++)
                    mma16816(acc[mt][nt], ah[mt], bb[nt]);   // hi*lo
        }
    }

    // ---- stage bias / v / dec_h for this CTA's 128 h ----------------------
    __syncthreads();
    if (tid < NT) {
        int h = n0 + tid;
        s_be[tid] = benc[h];
        s_v[tid]  = v[h];
        s_dh[tid] = g_dec_h[b * H_ + h];
    }
    __syncthreads();

    // ---- epilogue: y = acc+bias; flag; score += v*tanh(y+dec_h) -----------
    {
        float scr[4] = {0.f, 0.f, 0.f, 0.f};
        int   nzr[4] = {0, 0, 0, 0};
        const int n0w = wn * 64;
        #pragma unroll
        for (int mt = 0; mt < 2; mt++)
            #pragma unroll
            for (int nt = 0; nt < 8; nt++)
                #pragma unroll
                for (int c = 0; c < 4; c++) {
                    int rh = c >> 1, j = c & 1;
                    int hl = n0w + nt * 8 + t * 2 + j;
                    float y = acc[mt][nt][c] + s_be[hl];
                    int ri = mt * 2 + rh;
                    nzr[ri] |= (y != 0.f);
                    scr[ri] += s_v[hl] * tanhf(y + s_dh[hl]);
                }
        #pragma unroll
        for (int o = 1; o <= 2; o <<= 1)
            #pragma unroll
            for (int ri = 0; ri < 4; ri++) {
                scr[ri] += __shfl_xor_sync(0xffffffffu, scr[ri], o);
                nzr[ri] |= __shfl_xor_sync(0xffffffffu, nzr[ri], o);
            }
        if (t == 0) {
            #pragma unroll
            for (int ri = 0; ri < 4; ri++) {
                int row = wm * 32 + (ri >> 1) * 16 + (ri & 1) * 8 + g;
                s_red[row * 2 + wn] = scr[ri];
                s_nzr[row * 2 + wn] = nzr[ri];
            }
        }
    }
    __syncthreads();
    if (tid < MT) {
        float s = s_red[tid * 2] + s_red[tid * 2 + 1];
        int   f = s_nzr[tid * 2] | s_nzr[tid * 2 + 1];
        long gi = (mbase + tid) * NTILES + ntile;
        g_scpart[gi] = s;
        g_flpart[gi] = (unsigned char)(f != 0);
    }
}

// ---------------------------------------------------------------------------
// Kernel 2: combine N-tile partials, then masked softmax with ragged limit
// ---------------------------------------------------------------------------
__global__ void k_softmax() {
    const int b   = blockIdx.x;
    const int tid = threadIdx.x;  // 1024
    const int wid = tid >> 5, lane = tid & 31;
    __shared__ int   ri[32];
    __shared__ float rf[32];
    __shared__ int   s_limit;
    __shared__ float s_max, s_sum;

    int lmin = S_;
    for (int s = tid; s < S_; s += 1024) {
        long m4 = ((long)b * S_ + s) * NTILES;
        float sc = g_scpart[m4] + g_scpart[m4 + 1] + g_scpart[m4 + 2] + g_scpart[m4 + 3];
        int fl = g_flpart[m4] | g_flpart[m4 + 1] | g_flpart[m4 + 2] | g_flpart[m4 + 3];
        g_scores[b * S_ + s] = sc;
        if (!fl) lmin = min(lmin, s);
    }
    #pragma unroll
    for (int o = 16; o; o >>= 1) lmin = min(lmin, __shfl_xor_sync(0xffffffffu, lmin, o));
    if (lane == 0) ri[wid] = lmin;
    __syncthreads();
    if (tid < 32) {
        int vmin = ri[tid];
        #pragma unroll
        for (int o = 16; o; o >>= 1) vmin = min(vmin, __shfl_xor_sync(0xffffffffu, vmin, o));
        if (tid == 0) s_limit = vmin;
    }
    __syncthreads();
    const int limit = s_limit;

    float lmax = -INFINITY;
    for (int s = tid; s < limit; s += 1024) lmax = fmaxf(lmax, g_scores[b * S_ + s]);
    #pragma unroll
    for (int o = 16; o; o >>= 1) lmax = fmaxf(lmax, __shfl_xor_sync(0xffffffffu, lmax, o));
    if (lane == 0) rf[wid] = lmax;
    __syncthreads();
    if (tid < 32) {
        float vmax = rf[tid];
        #pragma unroll
        for (int o = 16; o; o >>= 1) vmax = fmaxf(vmax, __shfl_xor_sync(0xffffffffu, vmax, o));
        if (tid == 0) s_max = vmax;
    }
    __syncthreads();
    const float m = s_max;

    float lsum = 0.f;
    for (int s = tid; s < limit; s += 1024) lsum += expf(g_scores[b * S_ + s] - m);
    #pragma unroll
    for (int o = 16; o; o >>= 1) lsum += __shfl_xor_sync(0xffffffffu, lsum, o);
    __syncthreads();
    if (lane == 0) rf[wid] = lsum;
    __syncthreads();
    if (tid < 32) {
        float vs = rf[tid];
        #pragma unroll
        for (int o = 16; o; o >>= 1) vs += __shfl_xor_sync(0xffffffffu, vs, o);
        if (tid == 0) s_sum = vs;
    }
    __syncthreads();
    const float inv = (s_sum > 0.f) ? (1.f / s_sum) : 0.f;

    for (int s = tid; s < S_; s += 1024)
        g_attn[b * S_ + s] = (s < limit) ? expf(g_scores[b * S_ + s] - m) * inv : 0.f;
}

// ---------------------------------------------------------------------------
// Kernel 3: partial context sums over S-splits (deterministic, no atomics)
// ---------------------------------------------------------------------------
__global__ void k_context_part(const float* __restrict__ X) {
    const int b  = blockIdx.x;
    const int e  = blockIdx.y * 256 + threadIdx.x;
    const int ss = blockIdx.z;
    const int s0 = ss * (S_ / 8);
    __shared__ float at[S_ / 8];
    for (int i = threadIdx.x; i < S_ / 8; i += 256) at[i] = g_attn[b * S_ + s0 + i];
    __syncthreads();
    const float* Xp = X + ((long)b * S_ + s0) * E_ + e;
    float c = 0.f;
    #pragma unroll 8
    for (int s = 0; s < S_ / 8; s++) c = fmaf(at[s], Xp[(long)s * E_], c);
    g_partial[(b * 8 + ss) * E_ + e] = c;
}

// ---------------------------------------------------------------------------
// Kernel 4: reduce partials -> output [B,1,E]
// ---------------------------------------------------------------------------
__global__ void k_context_reduce(float* __restrict__ out) {
    const int b = blockIdx.x;
    const int e = threadIdx.x;  // 512
    float s = 0.f;
    #pragma unroll
    for (int k = 0; k < 8; k++) s += g_partial[(b * 8 + k) * E_ + e];
    out[b * E_ + e] = s;
}

extern "C" void kernel_launch(void* const* d_in, const int* in_sizes, int n_in,
                              void* d_out, int out_size) {
    const float* Xenc = (const float*)d_in[0];  // [B,S,E]
    const float* dec  = (const float*)d_in[1];  // [B,D]
    const float* Wenc = (const float*)d_in[2];  // [H,E]
    const float* benc = (const float*)d_in[3];  // [H]
    const float* Wdec = (const float*)d_in[4];  // [H,D]
    const float* bdec = (const float*)d_in[5];  // [H]
    const float* v    = (const float*)d_in[6];  // [H]
    float* out = (float*)d_out;                 // [B,1,E]

    k_convW<<<H_, 512>>>(Wenc);
    k_dec<<<B_, 256>>>(dec, Wdec, bdec);
    k_gemm<<<(B_ * S_ / MT) * NTILES, 256>>>(Xenc, benc, v);
    k_softmax<<<B_, 1024>>>();
    dim3 g3(B_, E_ / 256, 8);
    k_context_part<<<g3, 256>>>(Xenc);
    k_context_reduce<<<B_, E_>>>(out);
}

// round 14
// speedup vs baseline: 1.6934x; 1.6934x over previous
#include <cuda_runtime.h>
#include <cuda_fp16.h>
#include <math.h>
#include <stdint.h>

#define B_ 32
#define S_ 4096
#define E_ 512
#define D_ 512
#define H_ 512

#define MT 128          // CTA rows
#define NT 128          // CTA cols (h)
#define KC 32           // K chunk (fp32 source)
#define NCHUNK (E_ / KC)    // 16
#define NTILES (H_ / NT)    // 4
#define ASTR 40         // smem row stride in fp16 (pad: conflict-free frag loads)

// ---------------- scratch (__device__ globals; no allocs allowed) ----------
__device__ float          g_dec_h[B_ * H_];
__device__ __half         g_Wh[H_ * E_];
__device__ float          g_scpart[B_ * S_ * NTILES];
__device__ unsigned char  g_flpart[B_ * S_ * NTILES];
__device__ float          g_scores[B_ * S_];
__device__ float          g_attn[B_ * S_];
__device__ float          g_partial[B_ * 8 * E_];

// ---------------- mma.sync m16n8k16 fp16 (base ISA, valid on sm_103) -------
__device__ __forceinline__ void mma16816(float* d, const uint32_t* a,
                                         const uint32_t* b) {
    asm volatile(
        "mma.sync.aligned.m16n8k16.row.col.f32.f16.f16.f32 "
        "{%0,%1,%2,%3}, {%4,%5,%6,%7}, {%8,%9}, {%0,%1,%2,%3};"
        : "+f"(d[0]), "+f"(d[1]), "+f"(d[2]), "+f"(d[3])
        : "r"(a[0]), "r"(a[1]), "r"(a[2]), "r"(a[3]), "r"(b[0]), "r"(b[1]));
}

// ---------------------------------------------------------------------------
// Kernel A: convert W_enc to fp16 (0.5 MB, once per launch)
// ---------------------------------------------------------------------------
__global__ void k_convW(const float* __restrict__ W) {
    int i = blockIdx.x * 512 + threadIdx.x;
    g_Wh[i] = __float2half_rn(W[i]);
}

// ---------------------------------------------------------------------------
// Kernel 0: dec_h[b,h] = decoder_hidden[b,:] . W_dec[h,:] + b_dec[h]
// ---------------------------------------------------------------------------
__global__ void k_dec(const float* __restrict__ dec,
                      const float* __restrict__ Wd,
                      const float* __restrict__ bd) {
    int b = blockIdx.x;
    int warp = threadIdx.x >> 5, lane = threadIdx.x & 31, nw = blockDim.x >> 5;
    const float* drow = dec + (long)b * D_;
    for (int h = warp; h < H_; h += nw) {
        const float* wrow = Wd + (long)h * D_;
        float s = 0.f;
        for (int e = lane; e < D_; e += 32) s = fmaf(drow[e], wrow[e], s);
        #pragma unroll
        for (int o = 16; o; o >>= 1) s += __shfl_xor_sync(0xffffffffu, s, o);
        if (lane == 0) g_dec_h[b * H_ + h] = s + bd[h];
    }
}

// ---------------------------------------------------------------------------
// Kernel 1: fp16 single-pass HMMA GEMM + fused Bahdanau score epilogue.
// CTA = 128 rows x 128 h.  bid = mtile*4 + ntile.  8 warps as 4(M) x 2(N).
// ---------------------------------------------------------------------------
__global__ __launch_bounds__(256, 2)
void k_gemm(const float* __restrict__ X,
            const float* __restrict__ benc,
            const float* __restrict__ v) {
    __shared__ __half sAh[MT * ASTR];
    __shared__ __half sBh[NT * ASTR];
    __shared__ float s_red[MT * 2];
    __shared__ int   s_nzr[MT * 2];
    __shared__ float s_be[NT], s_v[NT], s_dh[NT];

    const int tid = threadIdx.x;
    const int wid = tid >> 5;
    const int lid = tid & 31;
    const int g   = lid >> 2;     // group id (rows / n within 8-blocks)
    const int t   = lid & 3;      // thread-in-group (k pairs)
    const int wm  = wid >> 1;     // warp M index 0..3 (32 rows each)
    const int wn  = wid & 1;      // warp N index 0..1 (64 cols each)

    const int mtile = blockIdx.x >> 2;
    const int ntile = blockIdx.x & 3;
    const int n0    = ntile * NT;
    const int b     = mtile >> 5;          // 32 M-tiles per batch
    const long mbase = (long)mtile * MT;

    float acc[2][8][4];
    #pragma unroll
    for (int mt = 0; mt < 2; mt++)
        #pragma unroll
        for (int nt = 0; nt < 8; nt++)
            #pragma unroll
            for (int c = 0; c < 4; c++) acc[mt][nt][c] = 0.f;

    const float* Xblk = X + mbase * E_;

    for (int ch = 0; ch < NCHUNK; ch++) {
        const int k0 = ch * KC;
        __syncthreads();
        // ---- stage A: 128 x 32 fp32 -> fp16 (1024 float4, 4/thread) -------
        #pragma unroll
        for (int it = 0; it < 4; it++) {
            int idx = tid + it * 256;
            int row = idx >> 3, q = idx & 7;        // q*4 = k offset
            float4 xv = *(const float4*)(Xblk + (long)row * E_ + k0 + q * 4);
            __half2 p0 = __floats2half2_rn(xv.x, xv.y);
            __half2 p1 = __floats2half2_rn(xv.z, xv.w);
            uint2 u = make_uint2(*(uint32_t*)&p0, *(uint32_t*)&p1);
            *(uint2*)&sAh[row * ASTR + q * 4] = u;
        }
        // ---- stage B: 128 h x 32 k from preconverted fp16 (512 uint4) -----
        #pragma unroll
        for (int it = 0; it < 2; it++) {
            int idx = tid + it * 256;
            int row = idx >> 2, q = idx & 3;        // q*8 = k offset
            long ge = (long)(n0 + row) * E_ + k0 + q * 8;
            *(uint4*)&sBh[row * ASTR + q * 8] = *(const uint4*)(g_Wh + ge);
        }
        __syncthreads();

        // ---- 2 k16 steps, single fp16 pass ---------------------------------
        #pragma unroll
        for (int ks = 0; ks < 2; ks++) {
            const int kb = ks * 16 + t * 2;
            uint32_t ah[2][4], bb[8][2];
            #pragma unroll
            for (int mt = 0; mt < 2; mt++) {
                int rb = wm * 32 + mt * 16 + g;
                ah[mt][0] = *(uint32_t*)&sAh[rb * ASTR + kb];
                ah[mt][1] = *(uint32_t*)&sAh[(rb + 8) * ASTR + kb];
                ah[mt][2] = *(uint32_t*)&sAh[rb * ASTR + kb + 8];
                ah[mt][3] = *(uint32_t*)&sAh[(rb + 8) * ASTR + kb + 8];
            }
            #pragma unroll
            for (int nt = 0; nt < 8; nt++) {
                int nr = wn * 64 + nt * 8 + g;
                bb[nt][0] = *(uint32_t*)&sBh[nr * ASTR + kb];
                bb[nt][1] = *(uint32_t*)&sBh[nr * ASTR + kb + 8];
            }
            #pragma unroll
            for (int mt = 0; mt < 2; mt++)
                #pragma unroll
                for (int nt = 0; nt < 8; nt++)
                    mma16816(acc[mt][nt], ah[mt], bb[nt]);
        }
    }

    // ---- stage bias / v / dec_h for this CTA's 128 h ----------------------
    __syncthreads();
    if (tid < NT) {
        int h = n0 + tid;
        s_be[tid] = benc[h];
        s_v[tid]  = v[h];
        s_dh[tid] = g_dec_h[b * H_ + h];
    }
    __syncthreads();

    // ---- epilogue: y = acc+bias; flag; score += v*tanh(y+dec_h) -----------
    {
        float scr[4] = {0.f, 0.f, 0.f, 0.f};
        int   nzr[4] = {0, 0, 0, 0};
        const int n0w = wn * 64;
        #pragma unroll
        for (int mt = 0; mt < 2; mt++)
            #pragma unroll
            for (int nt = 0; nt < 8; nt++)
                #pragma unroll
                for (int c = 0; c < 4; c++) {
                    int rh = c >> 1, j = c & 1;
                    int hl = n0w + nt * 8 + t * 2 + j;
                    float y = acc[mt][nt][c] + s_be[hl];
                    int ri = mt * 2 + rh;
                    nzr[ri] |= (y != 0.f);
                    scr[ri] += s_v[hl] * tanhf(y + s_dh[hl]);
                }
        #pragma unroll
        for (int o = 1; o <= 2; o <<= 1)
            #pragma unroll
            for (int ri = 0; ri < 4; ri++) {
                scr[ri] += __shfl_xor_sync(0xffffffffu, scr[ri], o);
                nzr[ri] |= __shfl_xor_sync(0xffffffffu, nzr[ri], o);
            }
        if (t == 0) {
            #pragma unroll
            for (int ri = 0; ri < 4; ri++) {
                int row = wm * 32 + (ri >> 1) * 16 + (ri & 1) * 8 + g;
                s_red[row * 2 + wn] = scr[ri];
                s_nzr[row * 2 + wn] = nzr[ri];
            }
        }
    }
    __syncthreads();
    if (tid < MT) {
        float s = s_red[tid * 2] + s_red[tid * 2 + 1];
        int   f = s_nzr[tid * 2] | s_nzr[tid * 2 + 1];
        long gi = (mbase + tid) * NTILES + ntile;
        g_scpart[gi] = s;
        g_flpart[gi] = (unsigned char)(f != 0);
    }
}

// ---------------------------------------------------------------------------
// Kernel 2: combine N-tile partials, then masked softmax with ragged limit
// ---------------------------------------------------------------------------
__global__ void k_softmax() {
    const int b   = blockIdx.x;
    const int tid = threadIdx.x;  // 1024
    const int wid = tid >> 5, lane = tid & 31;
    __shared__ int   ri[32];
    __shared__ float rf[32];
    __shared__ int   s_limit;
    __shared__ float s_max, s_sum;

    int lmin = S_;
    for (int s = tid; s < S_; s += 1024) {
        long m4 = ((long)b * S_ + s) * NTILES;
        float sc = g_scpart[m4] + g_scpart[m4 + 1] + g_scpart[m4 + 2] + g_scpart[m4 + 3];
        int fl = g_flpart[m4] | g_flpart[m4 + 1] | g_flpart[m4 + 2] | g_flpart[m4 + 3];
        g_scores[b * S_ + s] = sc;
        if (!fl) lmin = min(lmin, s);
    }
    #pragma unroll
    for (int o = 16; o; o >>= 1) lmin = min(lmin, __shfl_xor_sync(0xffffffffu, lmin, o));
    if (lane == 0) ri[wid] = lmin;
    __syncthreads();
    if (tid < 32) {
        int vmin = ri[tid];
        #pragma unroll
        for (int o = 16; o; o >>= 1) vmin = min(vmin, __shfl_xor_sync(0xffffffffu, vmin, o));
        if (tid == 0) s_limit = vmin;
    }
    __syncthreads();
    const int limit = s_limit;

    float lmax = -INFINITY;
    for (int s = tid; s < limit; s += 1024) lmax = fmaxf(lmax, g_scores[b * S_ + s]);
    #pragma unroll
    for (int o = 16; o; o >>= 1) lmax = fmaxf(lmax, __shfl_xor_sync(0xffffffffu, lmax, o));
    if (lane == 0) rf[wid] = lmax;
    __syncthreads();
    if (tid < 32) {
        float vmax = rf[tid];
        #pragma unroll
        for (int o = 16; o; o >>= 1) vmax = fmaxf(vmax, __shfl_xor_sync(0xffffffffu, vmax, o));
        if (tid == 0) s_max = vmax;
    }
    __syncthreads();
    const float m = s_max;

    float lsum = 0.f;
    for (int s = tid; s < limit; s += 1024) lsum += expf(g_scores[b * S_ + s] - m);
    #pragma unroll
    for (int o = 16; o; o >>= 1) lsum += __shfl_xor_sync(0xffffffffu, lsum, o);
    __syncthreads();
    if (lane == 0) rf[wid] = lsum;
    __syncthreads();
    if (tid < 32) {
        float vs = rf[tid];
        #pragma unroll
        for (int o = 16; o; o >>= 1) vs += __shfl_xor_sync(0xffffffffu, vs, o);
        if (tid == 0) s_sum = vs;
    }
    __syncthreads();
    const float inv = (s_sum > 0.f) ? (1.f / s_sum) : 0.f;

    for (int s = tid; s < S_; s += 1024)
        g_attn[b * S_ + s] = (s < limit) ? expf(g_scores[b * S_ + s] - m) * inv : 0.f;
}

// ---------------------------------------------------------------------------
// Kernel 3: partial context sums over S-splits (deterministic, no atomics)
// ---------------------------------------------------------------------------
__global__ void k_context_part(const float* __restrict__ X) {
    const int b  = blockIdx.x;
    const int e  = blockIdx.y * 256 + threadIdx.x;
    const int ss = blockIdx.z;
    const int s0 = ss * (S_ / 8);
    __shared__ float at[S_ / 8];
    for (int i = threadIdx.x; i < S_ / 8; i += 256) at[i] = g_attn[b * S_ + s0 + i];
    __syncthreads();
    const float* Xp = X + ((long)b * S_ + s0) * E_ + e;
    float c = 0.f;
    #pragma unroll 8
    for (int s = 0; s < S_ / 8; s++) c = fmaf(at[s], Xp[(long)s * E_], c);
    g_partial[(b * 8 + ss) * E_ + e] = c;
}

// ---------------------------------------------------------------------------
// Kernel 4: reduce partials -> output [B,1,E]
// ---------------------------------------------------------------------------
__global__ void k_context_reduce(float* __restrict__ out) {
    const int b = blockIdx.x;
    const int e = threadIdx.x;  // 512
    float s = 0.f;
    #pragma unroll
    for (int k = 0; k < 8; k++) s += g_partial[(b * 8 + k) * E_ + e];
    out[b * E_ + e] = s;
}

extern "C" void kernel_launch(void* const* d_in, const int* in_sizes, int n_in,
                              void* d_out, int out_size) {
    const float* Xenc = (const float*)d_in[0];  // [B,S,E]
    const float* dec  = (const float*)d_in[1];  // [B,D]
    const float* Wenc = (const float*)d_in[2];  // [H,E]
    const float* benc = (const float*)d_in[3];  // [H]
    const float* Wdec = (const float*)d_in[4];  // [H,D]
    const float* bdec = (const float*)d_in[5];  // [H]
    const float* v    = (const float*)d_in[6];  // [H]
    float* out = (float*)d_out;                 // [B,1,E]

    k_convW<<<H_, 512>>>(Wenc);
    k_dec<<<B_, 256>>>(dec, Wdec, bdec);
    k_gemm<<<(B_ * S_ / MT) * NTILES, 256>>>(Xenc, benc, v);
    k_softmax<<<B_, 1024>>>();
    dim3 g3(B_, E_ / 256, 8);
    k_context_part<<<g3, 256>>>(Xenc);
    k_context_reduce<<<B_, E_>>>(out);
}

// round 16
// speedup vs baseline: 2.4911x; 1.4711x over previous
#include <cuda_runtime.h>
#include <cuda_fp16.h>
#include <math.h>
#include <stdint.h>

#define B_ 32
#define S_ 4096
#define E_ 512
#define D_ 512
#define H_ 512

#define MT 128              // CTA rows
#define NT 128              // CTA cols (h)
#define KC2 64              // K chunk (fp16)
#define NCH2 (E_ / KC2)     // 8
#define NTILES (H_ / NT)    // 4
#define ASTR2 72            // smem row stride in halves (144B: ldmatrix conflict-free)
#define TILE_B (MT * ASTR2 * 2)   // 18432 bytes per tile
#define STAGE_B (2 * TILE_B)      // A+B per stage
#define DSMEM (2 * STAGE_B)       // 2 stages = 73728

// ---------------- scratch (__device__ globals; no allocs allowed) ----------
__device__ float          g_dec_h[B_ * H_];
__device__ __half         g_Wh[H_ * E_];
__device__ __half         g_Xh[(long)B_ * S_ * E_];   // 128 MB fp16 X
__device__ float          g_scpart[B_ * S_ * NTILES];
__device__ unsigned char  g_flpart[B_ * S_ * NTILES];
__device__ float          g_scores[B_ * S_];
__device__ float          g_attn[B_ * S_];
__device__ float          g_partial[B_ * 8 * E_];

// ---------------- PTX helpers (all base-ISA, valid on plain sm_103) --------
__device__ __forceinline__ uint32_t smem_u32(const void* p) {
    uint32_t a;
    asm("{ .reg .u64 t; cvta.to.shared.u64 t, %1; cvt.u32.u64 %0, t; }" : "=r"(a) : "l"(p));
    return a;
}

__device__ __forceinline__ void mma16816(float* d, const uint32_t* a,
                                         const uint32_t* b) {
    asm volatile(
        "mma.sync.aligned.m16n8k16.row.col.f32.f16.f16.f32 "
        "{%0,%1,%2,%3}, {%4,%5,%6,%7}, {%8,%9}, {%0,%1,%2,%3};"
        : "+f"(d[0]), "+f"(d[1]), "+f"(d[2]), "+f"(d[3])
        : "r"(a[0]), "r"(a[1]), "r"(a[2]), "r"(a[3]), "r"(b[0]), "r"(b[1]));
}

#define LDMX4(r0, r1, r2, r3, addr) \
    asm volatile("ldmatrix.sync.aligned.m8n8.x4.shared.b16 {%0,%1,%2,%3}, [%4];" \
        : "=r"(r0), "=r"(r1), "=r"(r2), "=r"(r3) : "r"(addr))

__device__ __forceinline__ void cp16(uint32_t saddr, const void* gaddr) {
    asm volatile("cp.async.cg.shared.global [%0], [%1], 16;"
                 :: "r"(saddr), "l"(gaddr) : "memory");
}

// stage one chunk (A from g_Xh, B from g_Wh) into a smem stage; one commit.
__device__ __forceinline__ void stage_chunk(int tid, long mbase, int n0, int ch,
                                            uint32_t sA, uint32_t sB) {
    const __half* Ag = g_Xh + mbase * E_ + ch * KC2;
    const __half* Bg = g_Wh + (long)n0 * E_ + ch * KC2;
    #pragma unroll
    for (int it = 0; it < 4; it++) {
        int idx = tid + it * 256;
        int row = idx >> 3, q = idx & 7;
        uint32_t so = (uint32_t)((row * ASTR2 + q * 8) * 2);
        cp16(sA + so, Ag + (long)row * E_ + q * 8);
        cp16(sB + so, Bg + (long)row * E_ + q * 8);
    }
    asm volatile("cp.async.commit_group;" ::: "memory");
}

// ---------------------------------------------------------------------------
// Kernel A1: W_enc -> fp16
// ---------------------------------------------------------------------------
__global__ void k_convW(const float* __restrict__ W) {
    int i = blockIdx.x * 512 + threadIdx.x;
    g_Wh[i] = __float2half_rn(W[i]);
}

// ---------------------------------------------------------------------------
// Kernel A2: X -> fp16 (8 elems/thread)
// ---------------------------------------------------------------------------
__global__ void k_convX(const float* __restrict__ X) {
    long i = ((long)blockIdx.x * 256 + threadIdx.x) * 8;
    float4 a = *(const float4*)(X + i);
    float4 b = *(const float4*)(X + i + 4);
    __half2 h0 = __floats2half2_rn(a.x, a.y);
    __half2 h1 = __floats2half2_rn(a.z, a.w);
    __half2 h2 = __floats2half2_rn(b.x, b.y);
    __half2 h3 = __floats2half2_rn(b.z, b.w);
    uint4 u = make_uint4(*(uint32_t*)&h0, *(uint32_t*)&h1,
                         *(uint32_t*)&h2, *(uint32_t*)&h3);
    *(uint4*)(g_Xh + i) = u;
}

// ---------------------------------------------------------------------------
// Kernel 0: dec_h[b,h] = decoder_hidden[b,:] . W_dec[h,:] + b_dec[h]
// grid = B*4, each block does 128 h of one batch.
// ---------------------------------------------------------------------------
__global__ void k_dec(const float* __restrict__ dec,
                      const float* __restrict__ Wd,
                      const float* __restrict__ bd) {
    int b  = blockIdx.x >> 2;
    int h0 = (blockIdx.x & 3) * 128;
    int warp = threadIdx.x >> 5, lane = threadIdx.x & 31;
    const float* drow = dec + (long)b * D_;
    for (int h = h0 + warp; h < h0 + 128; h += 8) {
        const float* wrow = Wd + (long)h * D_;
        float s = 0.f;
        for (int e = lane; e < D_; e += 32) s = fmaf(drow[e], wrow[e], s);
        #pragma unroll
        for (int o = 16; o; o >>= 1) s += __shfl_xor_sync(0xffffffffu, s, o);
        if (lane == 0) g_dec_h[b * H_ + h] = s + bd[h];
    }
}

// ---------------------------------------------------------------------------
// Kernel 1: fp16 HMMA GEMM, cp.async 2-stage pipeline, ldmatrix fragments,
// fused Bahdanau score epilogue. CTA = 128x128, 8 warps as 4(M) x 2(N).
// ---------------------------------------------------------------------------
__global__ __launch_bounds__(256, 2)
void k_gemm(const float* __restrict__ benc, const float* __restrict__ v) {
    extern __shared__ __half dsm[];
    __shared__ float s_red[MT * 2];
    __shared__ int   s_nzr[MT * 2];
    __shared__ float s_be[NT], s_v[NT], s_dh[NT];

    const int tid = threadIdx.x;
    const int wid = tid >> 5;
    const int lid = tid & 31;
    const int g   = lid >> 2;
    const int t   = lid & 3;
    const int wm  = wid >> 1;     // warp M 0..3
    const int wn  = wid & 1;      // warp N 0..1
    const int mi  = lid >> 3;     // ldmatrix matrix index 0..3
    const int r8  = lid & 7;

    const int mtile = blockIdx.x >> 2;
    const int ntile = blockIdx.x & 3;
    const int n0    = ntile * NT;
    const int b     = mtile >> 5;
    const long mbase = (long)mtile * MT;

    const uint32_t base = smem_u32(dsm);

    // ldmatrix per-lane byte offsets (within a tile)
    uint32_t aoff[2], boff[4];
    #pragma unroll
    for (int mt = 0; mt < 2; mt++)
        aoff[mt] = (uint32_t)(((wm * 32 + mt * 16 + (mi & 1) * 8 + r8) * ASTR2
                               + (mi >> 1) * 8) * 2);
    #pragma unroll
    for (int nb = 0; nb < 4; nb++)
        boff[nb] = (uint32_t)(((wn * 64 + (nb * 2 + (mi >> 1)) * 8 + r8) * ASTR2
                               + (mi & 1) * 8) * 2);

    float acc[2][8][4];
    #pragma unroll
    for (int mt = 0; mt < 2; mt++)
        #pragma unroll
        for (int nt = 0; nt < 8; nt++)
            #pragma unroll
            for (int c = 0; c < 4; c++) acc[mt][nt][c] = 0.f;

    // prologue: stage chunks 0,1
    stage_chunk(tid, mbase, n0, 0, base, base + TILE_B);
    stage_chunk(tid, mbase, n0, 1, base + STAGE_B, base + STAGE_B + TILE_B);

    for (int ch = 0; ch < NCH2; ch++) {
        if (ch == NCH2 - 1)
            asm volatile("cp.async.wait_group 0;" ::: "memory");
        else
            asm volatile("cp.async.wait_group 1;" ::: "memory");
        __syncthreads();

        const uint32_t uA = base + (ch & 1) * STAGE_B;
        const uint32_t uB = uA + TILE_B;
        #pragma unroll
        for (int ks = 0; ks < 4; ks++) {
            const uint32_t ko = (uint32_t)(ks * 32);
            uint32_t ah[2][4], bb[8][2];
            LDMX4(ah[0][0], ah[0][1], ah[0][2], ah[0][3], uA + aoff[0] + ko);
            LDMX4(ah[1][0], ah[1][1], ah[1][2], ah[1][3], uA + aoff[1] + ko);
            LDMX4(bb[0][0], bb[0][1], bb[1][0], bb[1][1], uB + boff[0] + ko);
            LDMX4(bb[2][0], bb[2][1], bb[3][0], bb[3][1], uB + boff[1] + ko);
            LDMX4(bb[4][0], bb[4][1], bb[5][0], bb[5][1], uB + boff[2] + ko);
            LDMX4(bb[6][0], bb[6][1], bb[7][0], bb[7][1], uB + boff[3] + ko);
            #pragma unroll
            for (int mt = 0; mt < 2; mt++)
                #pragma unroll
                for (int nt = 0; nt < 8; nt++)
                    mma16816(acc[mt][nt], ah[mt], bb[nt]);
        }
        __syncthreads();
        if (ch + 2 < NCH2)
            stage_chunk(tid, mbase, n0, ch + 2,
                        base + (ch & 1) * STAGE_B,
                        base + (ch & 1) * STAGE_B + TILE_B);
    }

    // ---- stage bias / v / dec_h for this CTA's 128 h ----------------------
    if (tid < NT) {
        int h = n0 + tid;
        s_be[tid] = benc[h];
        s_v[tid]  = v[h];
        s_dh[tid] = g_dec_h[b * H_ + h];
    }
    __syncthreads();

    // ---- epilogue: y = acc+bias; flag; score += v*tanh(y+dec_h) -----------
    {
        float scr[4] = {0.f, 0.f, 0.f, 0.f};
        int   nzr[4] = {0, 0, 0, 0};
        const int n0w = wn * 64;
        #pragma unroll
        for (int mt = 0; mt < 2; mt++)
            #pragma unroll
            for (int nt = 0; nt < 8; nt++)
                #pragma unroll
                for (int c = 0; c < 4; c++) {
                    int rh = c >> 1, j = c & 1;
                    int hl = n0w + nt * 8 + t * 2 + j;
                    float y = acc[mt][nt][c] + s_be[hl];
                    int ri = mt * 2 + rh;
                    nzr[ri] |= (y != 0.f);
                    scr[ri] += s_v[hl] * tanhf(y + s_dh[hl]);
                }
        #pragma unroll
        for (int o = 1; o <= 2; o <<= 1)
            #pragma unroll
            for (int ri = 0; ri < 4; ri++) {
                scr[ri] += __shfl_xor_sync(0xffffffffu, scr[ri], o);
                nzr[ri] |= __shfl_xor_sync(0xffffffffu, nzr[ri], o);
            }
        if (t == 0) {
            #pragma unroll
            for (int ri = 0; ri < 4; ri++) {
                int row = wm * 32 + (ri >> 1) * 16 + (ri & 1) * 8 + g;
                s_red[row * 2 + wn] = scr[ri];
                s_nzr[row * 2 + wn] = nzr[ri];
            }
        }
    }
    __syncthreads();
    if (tid < MT) {
        float s = s_red[tid * 2] + s_red[tid * 2 + 1];
        int   f = s_nzr[tid * 2] | s_nzr[tid * 2 + 1];
        long gi = (mbase + tid) * NTILES + ntile;
        g_scpart[gi] = s;
        g_flpart[gi] = (unsigned char)(f != 0);
    }
}

// ---------------------------------------------------------------------------
// Kernel 2: combine N-tile partials, then masked softmax with ragged limit
// ---------------------------------------------------------------------------
__global__ void k_softmax() {
    const int b   = blockIdx.x;
    const int tid = threadIdx.x;  // 1024
    const int wid = tid >> 5, lane = tid & 31;
    __shared__ int   ri[32];
    __shared__ float rf[32];
    __shared__ int   s_limit;
    __shared__ float s_max, s_sum;

    int lmin = S_;
    for (int s = tid; s < S_; s += 1024) {
        long m4 = ((long)b * S_ + s) * NTILES;
        float sc = g_scpart[m4] + g_scpart[m4 + 1] + g_scpart[m4 + 2] + g_scpart[m4 + 3];
        int fl = g_flpart[m4] | g_flpart[m4 + 1] | g_flpart[m4 + 2] | g_flpart[m4 + 3];
        g_scores[b * S_ + s] = sc;
        if (!fl) lmin = min(lmin, s);
    }
    #pragma unroll
    for (int o = 16; o; o >>= 1) lmin = min(lmin, __shfl_xor_sync(0xffffffffu, lmin, o));
    if (lane == 0) ri[wid] = lmin;
    __syncthreads();
    if (tid < 32) {
        int vmin = ri[tid];
        #pragma unroll
        for (int o = 16; o; o >>= 1) vmin = min(vmin, __shfl_xor_sync(0xffffffffu, vmin, o));
        if (tid == 0) s_limit = vmin;
    }
    __syncthreads();
    const int limit = s_limit;

    float lmax = -INFINITY;
    for (int s = tid; s < limit; s += 1024) lmax = fmaxf(lmax, g_scores[b * S_ + s]);
    #pragma unroll
    for (int o = 16; o; o >>= 1) lmax = fmaxf(lmax, __shfl_xor_sync(0xffffffffu, lmax, o));
    if (lane == 0) rf[wid] = lmax;
    __syncthreads();
    if (tid < 32) {
        float vmax = rf[tid];
        #pragma unroll
        for (int o = 16; o; o >>= 1) vmax = fmaxf(vmax, __shfl_xor_sync(0xffffffffu, vmax, o));
        if (tid == 0) s_max = vmax;
    }
    __syncthreads();
    const float m = s_max;

    float lsum = 0.f;
    for (int s = tid; s < limit; s += 1024) lsum += expf(g_scores[b * S_ + s] - m);
    #pragma unroll
    for (int o = 16; o; o >>= 1) lsum += __shfl_xor_sync(0xffffffffu, lsum, o);
    __syncthreads();
    if (lane == 0) rf[wid] = lsum;
    __syncthreads();
    if (tid < 32) {
        float vs = rf[tid];
        #pragma unroll
        for (int o = 16; o; o >>= 1) vs += __shfl_xor_sync(0xffffffffu, vs, o);
        if (tid == 0) s_sum = vs;
    }
    __syncthreads();
    const float inv = (s_sum > 0.f) ? (1.f / s_sum) : 0.f;

    for (int s = tid; s < S_; s += 1024)
        g_attn[b * S_ + s] = (s < limit) ? expf(g_scores[b * S_ + s] - m) * inv : 0.f;
}

// ---------------------------------------------------------------------------
// Kernel 3: partial context sums over S-splits, reading fp16 X (half traffic)
// ---------------------------------------------------------------------------
__global__ void k_context_part() {
    const int b  = blockIdx.x;
    const int e  = blockIdx.y * 256 + threadIdx.x;
    const int ss = blockIdx.z;
    const int s0 = ss * (S_ / 8);
    __shared__ float at[S_ / 8];
    for (int i = threadIdx.x; i < S_ / 8; i += 256) at[i] = g_attn[b * S_ + s0 + i];
    __syncthreads();
    const __half* Xp = g_Xh + ((long)b * S_ + s0) * E_ + e;
    float c = 0.f;
    #pragma unroll 8
    for (int s = 0; s < S_ / 8; s++)
        c = fmaf(at[s], __half2float(Xp[(long)s * E_]), c);
    g_partial[(b * 8 + ss) * E_ + e] = c;
}

// ---------------------------------------------------------------------------
// Kernel 4: reduce partials -> output [B,1,E]
// ---------------------------------------------------------------------------
__global__ void k_context_reduce(float* __restrict__ out) {
    const int b = blockIdx.x;
    const int e = threadIdx.x;  // 512
    float s = 0.f;
    #pragma unroll
    for (int k = 0; k < 8; k++) s += g_partial[(b * 8 + k) * E_ + e];
    out[b * E_ + e] = s;
}

extern "C" void kernel_launch(void* const* d_in, const int* in_sizes, int n_in,
                              void* d_out, int out_size) {
    const float* Xenc = (const float*)d_in[0];  // [B,S,E]
    const float* dec  = (const float*)d_in[1];  // [B,D]
    const float* Wenc = (const float*)d_in[2];  // [H,E]
    const float* benc = (const float*)d_in[3];  // [H]
    const float* Wdec = (const float*)d_in[4];  // [H,D]
    const float* bdec = (const float*)d_in[5];  // [H]
    const float* v    = (const float*)d_in[6];  // [H]
    float* out = (float*)d_out;                 // [B,1,E]

    cudaFuncSetAttribute(k_gemm, cudaFuncAttributeMaxDynamicSharedMemorySize, DSMEM);

    k_convW<<<H_, 512>>>(Wenc);
    k_convX<<<(int)(((long)B_ * S_ * E_) / (256 * 8)), 256>>>(Xenc);
    k_dec<<<B_ * 4, 256>>>(dec, Wdec, bdec);
    k_gemm<<<(B_ * S_ / MT) * NTILES, 256, DSMEM>>>(benc, v);
    k_softmax<<<B_, 1024>>>();
    dim3 g3(B_, E_ / 256, 8);
    k_context_part<<<g3, 256>>>();
    k_context_reduce<<<B_, E_>>>(out);
}